// round 5
// baseline (speedup 1.0000x reference)
#include <cuda_runtime.h>
#include <cuda_bf16.h>
#include <math.h>

#define BB 4
#define TT 2048
#define CC 1024
#define HH 2048

typedef unsigned long long ull;

// Scratch (device globals: allocation-free rule)
__device__ float g_q[(size_t)BB * TT * HH];
__device__ float g_k[(size_t)BB * TT * HH];
__device__ float g_v[(size_t)BB * TT * HH];
__device__ float g_s[(size_t)BB * TT * TT];

// ---- f32x2 packed helpers (Blackwell FFMA2 path) --------------------------
__device__ __forceinline__ ull pack2(float lo, float hi) {
    ull r; asm("mov.b64 %0, {%1, %2};" : "=l"(r) : "f"(lo), "f"(hi)); return r;
}
__device__ __forceinline__ void fma2(ull& d, ull a, ull b) {
    asm("fma.rn.f32x2 %0, %1, %2, %0;" : "+l"(d) : "l"(a), "l"(b));
}
__device__ __forceinline__ ull mul2(ull a, ull b) {
    ull r; asm("mul.rn.f32x2 %0, %1, %2;" : "=l"(r) : "l"(a), "l"(b)); return r;
}

// ---------------------------------------------------------------------------
// C = scale * A * B^T   (A: [M,K] rm, B: [N,K] rm, C: [M,N])
// 128x128 tile, BK=8, 256 threads, 8x8 microtile, f32x2 accumulators,
// double-buffered smem. A stored DUPLICATED in smem so the broadcast operand
// loads directly as a 64-bit lane pair (no per-k pack).
// causal: skip blocks with bx > by.
// ---------------------------------------------------------------------------
__global__ __launch_bounds__(256, 2)
void sgemm_nt(const float* __restrict__ A, const float* __restrict__ B,
              float* __restrict__ C, int M, int N, int K, float scale,
              int causal, long long sA, long long sB, long long sC)
{
    int bz = blockIdx.z;
    A += (long long)bz * sA;
    B += (long long)bz * sB;
    C += (long long)bz * sC;

    int bx = blockIdx.x;   // N-block
    int by = blockIdx.y;   // M-block
    if (causal && bx > by) return;

    __shared__ float As[2][8][256];   // duplicated pairs: [k][2*row(+0/1)]
    __shared__ float Bs[2][8][128];

    int tid = threadIdx.x;
    int tx = tid & 15;     // col group (8 cols = 4 pairs)
    int ty = tid >> 4;     // row group (8 rows)

    int lrow = tid >> 1;          // 0..127
    int lcol = (tid & 1) * 4;     // 0 or 4

    const float* Aptr = A + (long long)(by * 128 + lrow) * K + lcol;
    const float* Bptr = B + (long long)(bx * 128 + lrow) * K + lcol;

    ull acc[8][4];
#pragma unroll
    for (int i = 0; i < 8; i++)
#pragma unroll
        for (int j = 0; j < 4; j++) acc[i][j] = 0ull;

    int nt = K >> 3;

    // preload tile 0
    float4 av = *(const float4*)(Aptr);
    float4 bv = *(const float4*)(Bptr);
    {
        float a4[4] = {av.x, av.y, av.z, av.w};
        float b4[4] = {bv.x, bv.y, bv.z, bv.w};
#pragma unroll
        for (int j = 0; j < 4; j++) {
            *(ull*)&As[0][lcol + j][2 * lrow] = pack2(a4[j], a4[j]);
            Bs[0][lcol + j][lrow] = b4[j];
        }
    }
    __syncthreads();

    for (int t = 0; t < nt; t++) {
        int cur = t & 1;
        if (t + 1 < nt) {
            av = *(const float4*)(Aptr + (t + 1) * 8);
            bv = *(const float4*)(Bptr + (t + 1) * 8);
        }

#pragma unroll
        for (int k = 0; k < 8; k++) {
            ull a2[8], b2[4];
            const ull* ap = (const ull*)&As[cur][k][ty * 16];
            const ull* bp = (const ull*)&Bs[cur][k][tx * 8];
#pragma unroll
            for (int i = 0; i < 8; i++) a2[i] = ap[i];
#pragma unroll
            for (int j = 0; j < 4; j++) b2[j] = bp[j];
#pragma unroll
            for (int i = 0; i < 8; i++)
#pragma unroll
                for (int j = 0; j < 4; j++)
                    fma2(acc[i][j], a2[i], b2[j]);
        }

        if (t + 1 < nt) {
            int nxt = cur ^ 1;
            float a4[4] = {av.x, av.y, av.z, av.w};
            float b4[4] = {bv.x, bv.y, bv.z, bv.w};
#pragma unroll
            for (int j = 0; j < 4; j++) {
                *(ull*)&As[nxt][lcol + j][2 * lrow] = pack2(a4[j], a4[j]);
                Bs[nxt][lcol + j][lrow] = b4[j];
            }
        }
        __syncthreads();
    }

    ull sc2 = pack2(scale, scale);
#pragma unroll
    for (int i = 0; i < 8; i++) {
        int r = by * 128 + ty * 8 + i;
        float* cp = C + (long long)r * N + bx * 128 + tx * 8;
        ulonglong2 u;
        u.x = mul2(acc[i][0], sc2); u.y = mul2(acc[i][1], sc2);
        *(ulonglong2*)(cp) = u;
        u.x = mul2(acc[i][2], sc2); u.y = mul2(acc[i][3], sc2);
        *(ulonglong2*)(cp + 4) = u;
    }
}

// ---------------------------------------------------------------------------
// C = A * B   (A: [M,K] rm, B: [K,N] rm, C: [M,N]), f32x2 + double buffer.
// causal_klimit: k-loop bounded at (by+1)*128 (valid P columns only)
// ---------------------------------------------------------------------------
__global__ __launch_bounds__(256, 2)
void sgemm_nn(const float* __restrict__ A, const float* __restrict__ B,
              float* __restrict__ C, int M, int N, int K,
              int causal_klimit, long long sA, long long sB, long long sC)
{
    int bz = blockIdx.z;
    A += (long long)bz * sA;
    B += (long long)bz * sB;
    C += (long long)bz * sC;

    int bx = blockIdx.x;   // N-block
    int by = blockIdx.y;   // M-block

    __shared__ float As[2][8][256];   // duplicated
    __shared__ float Bs[2][8][128];

    int tid = threadIdx.x;
    int tx = tid & 15;
    int ty = tid >> 4;

    int larow = tid >> 1;
    int lacol = (tid & 1) * 4;
    int lbrow = tid >> 5;          // 0..7
    int lbcol = (tid & 31) * 4;    // 0..124

    const float* Aptr = A + (long long)(by * 128 + larow) * K + lacol;
    const float* Bptr = B + (long long)lbrow * N + bx * 128 + lbcol;

    int kend = causal_klimit ? min(K, (by + 1) * 128) : K;
    int nt = kend >> 3;

    ull acc[8][4];
#pragma unroll
    for (int i = 0; i < 8; i++)
#pragma unroll
        for (int j = 0; j < 4; j++) acc[i][j] = 0ull;

    float4 av = *(const float4*)(Aptr);
    float4 bv = *(const float4*)(Bptr);
    {
        float a4[4] = {av.x, av.y, av.z, av.w};
#pragma unroll
        for (int j = 0; j < 4; j++)
            *(ull*)&As[0][lacol + j][2 * larow] = pack2(a4[j], a4[j]);
        *(float4*)&Bs[0][lbrow][lbcol] = bv;
    }
    __syncthreads();

    for (int t = 0; t < nt; t++) {
        int cur = t & 1;
        if (t + 1 < nt) {
            av = *(const float4*)(Aptr + (t + 1) * 8);
            bv = *(const float4*)(Bptr + (long long)(t + 1) * 8 * N);
        }

#pragma unroll
        for (int k = 0; k < 8; k++) {
            ull a2[8], b2[4];
            const ull* ap = (const ull*)&As[cur][k][ty * 16];
            const ull* bp = (const ull*)&Bs[cur][k][tx * 8];
#pragma unroll
            for (int i = 0; i < 8; i++) a2[i] = ap[i];
#pragma unroll
            for (int j = 0; j < 4; j++) b2[j] = bp[j];
#pragma unroll
            for (int i = 0; i < 8; i++)
#pragma unroll
                for (int j = 0; j < 4; j++)
                    fma2(acc[i][j], a2[i], b2[j]);
        }

        if (t + 1 < nt) {
            int nxt = cur ^ 1;
            float a4[4] = {av.x, av.y, av.z, av.w};
#pragma unroll
            for (int j = 0; j < 4; j++)
                *(ull*)&As[nxt][lacol + j][2 * larow] = pack2(a4[j], a4[j]);
            *(float4*)&Bs[nxt][lbrow][lbcol] = bv;
        }
        __syncthreads();
    }

#pragma unroll
    for (int i = 0; i < 8; i++) {
        int r = by * 128 + ty * 8 + i;
        float* cp = C + (long long)r * N + bx * 128 + tx * 8;
        ulonglong2 u;
        u.x = acc[i][0]; u.y = acc[i][1];
        *(ulonglong2*)(cp) = u;
        u.x = acc[i][2]; u.y = acc[i][3];
        *(ulonglong2*)(cp + 4) = u;
    }
}

// ---------------------------------------------------------------------------
// Causal row softmax in-place on S[B,T,T]. One block per row.
// Also zero-fills (t, diag-block end) so PV GEMM needs no masking.
// ---------------------------------------------------------------------------
__device__ __forceinline__ float warp_max(float v) {
#pragma unroll
    for (int o = 16; o; o >>= 1) v = fmaxf(v, __shfl_xor_sync(0xffffffffu, v, o));
    return v;
}
__device__ __forceinline__ float warp_sum(float v) {
#pragma unroll
    for (int o = 16; o; o >>= 1) v += __shfl_xor_sync(0xffffffffu, v, o);
    return v;
}

__global__ __launch_bounds__(256)
void softmax_causal(float* __restrict__ S, int T)
{
    int row = blockIdx.x;
    int b = row / T;
    int t = row - b * T;
    float* p = S + (long long)b * T * T + (long long)t * T;
    int n = t + 1;

    int tid = threadIdx.x;
    int lane = tid & 31, wid = tid >> 5;
    __shared__ float red[8];

    float m = -INFINITY;
    for (int i = tid; i < n; i += 256) m = fmaxf(m, p[i]);
    m = warp_max(m);
    if (lane == 0) red[wid] = m;
    __syncthreads();
    if (wid == 0) {
        float x = (lane < 8) ? red[lane] : -INFINITY;
        x = warp_max(x);
        if (lane == 0) red[0] = x;
    }
    __syncthreads();
    m = red[0];
    __syncthreads();

    float s = 0.f;
    for (int i = tid; i < n; i += 256) {
        float e = __expf(p[i] - m);
        p[i] = e;
        s += e;
    }
    s = warp_sum(s);
    if (lane == 0) red[wid] = s;
    __syncthreads();
    if (wid == 0) {
        float x = (lane < 8) ? red[lane] : 0.f;
        x = warp_sum(x);
        if (lane == 0) red[0] = x;
    }
    __syncthreads();
    float inv = 1.f / red[0];

    for (int i = tid; i < n; i += 256) p[i] *= inv;

    int zend = min(T, ((t >> 7) + 1) << 7);
    for (int i = n + tid; i < zend; i += 256) p[i] = 0.f;
}

// ---------------------------------------------------------------------------
extern "C" void kernel_launch(void* const* d_in, const int* in_sizes, int n_in,
                              void* d_out, int out_size)
{
    const float* x  = (const float*)d_in[0];   // [B,T,C]
    const float* Wk = (const float*)d_in[1];   // [H,C]
    const float* Wq = (const float*)d_in[2];   // [H,C]
    const float* Wv = (const float*)d_in[3];   // [H,C]
    float* out = (float*)d_out;                // [B,T,H]

    float* q; cudaGetSymbolAddress((void**)&q, g_q);
    float* k; cudaGetSymbolAddress((void**)&k, g_k);
    float* v; cudaGetSymbolAddress((void**)&v, g_v);
    float* s; cudaGetSymbolAddress((void**)&s, g_s);

    const int M = BB * TT;           // 8192
    const float scale = rsqrtf((float)HH);

    // 1) Projections: [M,C] x [H,C]^T -> [M,H]
    dim3 gp(HH / 128, M / 128, 1);
    sgemm_nt<<<gp, 256>>>(x, Wq, q, M, HH, CC, 1.f, 0, 0, 0, 0);
    sgemm_nt<<<gp, 256>>>(x, Wk, k, M, HH, CC, 1.f, 0, 0, 0, 0);
    sgemm_nt<<<gp, 256>>>(x, Wv, v, M, HH, CC, 1.f, 0, 0, 0, 0);

    // 2) Scores: S_b = scale * Q_b K_b^T   (causal block skip)
    dim3 gs(TT / 128, TT / 128, BB);
    sgemm_nt<<<gs, 256>>>(q, k, s, TT, TT, HH, scale, 1,
                          (long long)TT * HH, (long long)TT * HH,
                          (long long)TT * TT);

    // 3) Causal softmax rows (in-place) + zero diag-block tail
    softmax_causal<<<BB * TT, 256>>>(s, TT);

    // 4) O_b = P_b V_b  (k-loop limited per block row)
    dim3 go(HH / 128, TT / 128, BB);
    sgemm_nn<<<go, 256>>>(s, v, out, TT, HH, TT, 1,
                          (long long)TT * TT, (long long)TT * HH,
                          (long long)TT * HH);
}

// round 9
// speedup vs baseline: 3.3196x; 3.3196x over previous
#include <cuda_runtime.h>
#include <cstdint>
#include <math.h>

#define BB 4
#define TT 2048
#define CC 1024
#define HH 2048

// ---- scratch (device globals; allocation-free rule) -----------------------
__device__ float g_q[(size_t)BB * TT * HH];
__device__ float g_k[(size_t)BB * TT * HH];
__device__ float g_v[(size_t)BB * TT * HH];      // V TRANSPOSED: [B][H][T]
__device__ float g_s[(size_t)BB * TT * TT];
__device__ float g_xr[(size_t)BB * TT * CC];     // tf32-rounded x
__device__ float g_wr[(size_t)3 * HH * CC];      // tf32-rounded Wk|Wq|Wv

// ---- helpers --------------------------------------------------------------
__device__ __forceinline__ uint32_t smem_u32(const void* p) {
    uint32_t a;
    asm("{ .reg .u64 t; cvta.to.shared.u64 t, %1; cvt.u32.u64 %0, t; }"
        : "=r"(a) : "l"(p));
    return a;
}
__device__ __forceinline__ float tf32r(float v) {
    uint32_t u;
    asm("cvt.rna.tf32.f32 %0, %1;" : "=r"(u) : "f"(v));
    return __uint_as_float(u);
}

#define CP16(dst, src) \
    asm volatile("cp.async.cg.shared.global [%0], [%1], 16;" \
                 :: "r"(dst), "l"(src))
#define CP_COMMIT() asm volatile("cp.async.commit_group;" ::: "memory")
#define CP_WAIT1()  asm volatile("cp.async.wait_group 1;" ::: "memory")
#define CP_WAIT0()  asm volatile("cp.async.wait_group 0;" ::: "memory")

#define LDSM4(r0, r1, r2, r3, a) \
    asm volatile("ldmatrix.sync.aligned.m8n8.x4.shared.b16 {%0,%1,%2,%3}, [%4];" \
                 : "=r"(r0), "=r"(r1), "=r"(r2), "=r"(r3) : "r"(a))
#define LDSM2(r0, r1, a) \
    asm volatile("ldmatrix.sync.aligned.m8n8.x2.shared.b16 {%0,%1}, [%2];" \
                 : "=r"(r0), "=r"(r1) : "r"(a))

#define MMA8(d, a, b) \
    asm volatile("mma.sync.aligned.m16n8k8.row.col.f32.tf32.tf32.f32 " \
        "{%0,%1,%2,%3}, {%4,%5,%6,%7}, {%8,%9}, {%0,%1,%2,%3};" \
        : "+f"((d)[0]), "+f"((d)[1]), "+f"((d)[2]), "+f"((d)[3]) \
        : "r"((a)[0]), "r"((a)[1]), "r"((a)[2]), "r"((a)[3]), \
          "r"((b)[0]), "r"((b)[1]))

// ---- GEMM config ----------------------------------------------------------
#define BM 128
#define BN 128
#define BK 16
#define PADK 20                         // floats per smem row (80B: LDSM conflict-free)
#define TBUF (BM * PADK)                // floats per buffer
#define TBUF_B (TBUF * 4)               // bytes

// ---------------------------------------------------------------------------
// C[M,N] = scale * A[M,K] * B[N,K]^T   (both row-major, K contiguous)
// tf32 mma.sync, 128x128x16 tiles, 8 warps (2x4), warp tile 64x32,
// cp.async double buffer, ldmatrix fragments.
// causal: skip tiles bx > by.   klimit: K bounded at (by+1)*BM.
// round_out: round outputs to tf32 (RNA) — for tensors feeding another MMA.
// ---------------------------------------------------------------------------
__global__ __launch_bounds__(256)
void mma_nt(const float* __restrict__ A, const float* __restrict__ B,
            float* __restrict__ C, int M, int N, int K, float scale,
            int causal, int klimit, int round_out,
            long long sA, long long sB, long long sC)
{
    int bx = blockIdx.x, by = blockIdx.y, bz = blockIdx.z;
    if (causal && bx > by) return;
    A += (long long)bz * sA;
    B += (long long)bz * sB;
    C += (long long)bz * sC;

    __shared__ float As[2][TBUF];
    __shared__ float Bs[2][TBUF];

    int tid = threadIdx.x;
    int lane = tid & 31, wid = tid >> 5;
    int warp_m = wid >> 2;              // 0..1 -> 64-row half
    int warp_n = wid & 3;               // 0..3 -> 32-col quarter

    const float* Ab = A + (size_t)(by * BM) * K;
    const float* Bb = B + (size_t)(bx * BN) * K;

    int kend = klimit ? min(K, (by + 1) * BM) : K;
    int nt = kend / BK;

    uint32_t as0 = smem_u32(As);
    uint32_t bs0 = smem_u32(Bs);

    // cp.async chunk mapping: 512 16B-chunks per matrix, 2 per thread
    int ch0 = tid * 2, ch1 = tid * 2 + 1;
    int ra0 = ch0 >> 2, ca0 = ch0 & 3;
    int ra1 = ch1 >> 2, ca1 = ch1 & 3;
    uint32_t dA0 = as0 + (uint32_t)(ra0 * PADK + ca0 * 4) * 4;
    uint32_t dA1 = as0 + (uint32_t)(ra1 * PADK + ca1 * 4) * 4;
    uint32_t dB0 = bs0 + (uint32_t)(ra0 * PADK + ca0 * 4) * 4;
    uint32_t dB1 = bs0 + (uint32_t)(ra1 * PADK + ca1 * 4) * 4;
    const float* sA0 = Ab + (size_t)ra0 * K + ca0 * 4;
    const float* sA1 = Ab + (size_t)ra1 * K + ca1 * 4;
    const float* sB0 = Bb + (size_t)ra0 * K + ca0 * 4;
    const float* sB1 = Bb + (size_t)ra1 * K + ca1 * 4;

    // ldmatrix per-lane base addresses
    // A (x4): lanes 0-7 rows 0-7, 8-15 rows 8-15, 16-23 rows 0-7 (+4 cols),
    //         24-31 rows 8-15 (+4 cols)
    uint32_t aAddr = as0 + (uint32_t)(((warp_m * 64 + (lane & 15)) * PADK
                                       + (lane >> 4) * 4) * 4);
    // B (x2): lanes 0-7 rows, 8-15 same rows +4 cols
    uint32_t bAddr = bs0 + (uint32_t)(((warp_n * 32 + (lane & 7)) * PADK
                                       + ((lane >> 3) & 1) * 4) * 4);

    float acc[4][4][4];
#pragma unroll
    for (int i = 0; i < 4; i++)
#pragma unroll
        for (int j = 0; j < 4; j++)
#pragma unroll
            for (int r = 0; r < 4; r++) acc[i][j][r] = 0.f;

    // preload tile 0
    CP16(dA0, sA0); CP16(dA1, sA1);
    CP16(dB0, sB0); CP16(dB1, sB1);
    CP_COMMIT();

    for (int t = 0; t < nt; t++) {
        uint32_t boff = (uint32_t)(t & 1) * TBUF_B;
        if (t + 1 < nt) {
            uint32_t nboff = (uint32_t)((t + 1) & 1) * TBUF_B;
            size_t ko = (size_t)(t + 1) * BK;
            CP16(dA0 + nboff, sA0 + ko); CP16(dA1 + nboff, sA1 + ko);
            CP16(dB0 + nboff, sB0 + ko); CP16(dB1 + nboff, sB1 + ko);
            CP_COMMIT();
            CP_WAIT1();
        } else {
            CP_WAIT0();
        }
        __syncthreads();

#pragma unroll
        for (int ks = 0; ks < 2; ks++) {
            uint32_t a[4][4], b[4][2];
#pragma unroll
            for (int mi = 0; mi < 4; mi++)
                LDSM4(a[mi][0], a[mi][1], a[mi][2], a[mi][3],
                      aAddr + boff + (uint32_t)(mi * 16 * PADK * 4 + ks * 32));
#pragma unroll
            for (int ni = 0; ni < 4; ni++)
                LDSM2(b[ni][0], b[ni][1],
                      bAddr + boff + (uint32_t)(ni * 8 * PADK * 4 + ks * 32));
#pragma unroll
            for (int mi = 0; mi < 4; mi++)
#pragma unroll
                for (int ni = 0; ni < 4; ni++)
                    MMA8(acc[mi][ni], a[mi], b[ni]);
        }
        __syncthreads();
    }

    // epilogue
#pragma unroll
    for (int mi = 0; mi < 4; mi++) {
#pragma unroll
        for (int ni = 0; ni < 4; ni++) {
            int r0 = by * BM + warp_m * 64 + mi * 16 + (lane >> 2);
            int c  = bx * BN + warp_n * 32 + ni * 8 + 2 * (lane & 3);
            float2 v0, v1;
            v0.x = acc[mi][ni][0] * scale; v0.y = acc[mi][ni][1] * scale;
            v1.x = acc[mi][ni][2] * scale; v1.y = acc[mi][ni][3] * scale;
            if (round_out) {
                v0.x = tf32r(v0.x); v0.y = tf32r(v0.y);
                v1.x = tf32r(v1.x); v1.y = tf32r(v1.y);
            }
            *(float2*)(C + (size_t)r0 * N + c)       = v0;
            *(float2*)(C + (size_t)(r0 + 8) * N + c) = v1;
        }
    }
}

// ---- tf32 pre-rounding pass ----------------------------------------------
__global__ __launch_bounds__(256)
void round_pass(const float* __restrict__ in, float* __restrict__ out, int n)
{
    int i = (blockIdx.x * 256 + threadIdx.x) * 4;
    if (i < n) {
        float4 v = *(const float4*)(in + i);
        v.x = tf32r(v.x); v.y = tf32r(v.y); v.z = tf32r(v.z); v.w = tf32r(v.w);
        *(float4*)(out + i) = v;
    }
}

// ---- causal softmax (in-place), rounds P to tf32, zero-fills diag tail ----
__device__ __forceinline__ float warp_max(float v) {
#pragma unroll
    for (int o = 16; o; o >>= 1) v = fmaxf(v, __shfl_xor_sync(0xffffffffu, v, o));
    return v;
}
__device__ __forceinline__ float warp_sum(float v) {
#pragma unroll
    for (int o = 16; o; o >>= 1) v += __shfl_xor_sync(0xffffffffu, v, o);
    return v;
}

__global__ __launch_bounds__(256)
void softmax_causal(float* __restrict__ S, int T)
{
    int row = blockIdx.x;
    int b = row / T;
    int t = row - b * T;
    float* p = S + (long long)b * T * T + (long long)t * T;
    int n = t + 1;

    int tid = threadIdx.x;
    int lane = tid & 31, wid = tid >> 5;
    __shared__ float red[8];

    float m = -INFINITY;
    for (int i = tid; i < n; i += 256) m = fmaxf(m, p[i]);
    m = warp_max(m);
    if (lane == 0) red[wid] = m;
    __syncthreads();
    if (wid == 0) {
        float x = (lane < 8) ? red[lane] : -INFINITY;
        x = warp_max(x);
        if (lane == 0) red[0] = x;
    }
    __syncthreads();
    m = red[0];
    __syncthreads();

    float s = 0.f;
    for (int i = tid; i < n; i += 256) {
        float e = __expf(p[i] - m);
        p[i] = e;
        s += e;
    }
    s = warp_sum(s);
    if (lane == 0) red[wid] = s;
    __syncthreads();
    if (wid == 0) {
        float x = (lane < 8) ? red[lane] : 0.f;
        x = warp_sum(x);
        if (lane == 0) red[0] = x;
    }
    __syncthreads();
    float inv = 1.f / red[0];

    for (int i = tid; i < n; i += 256) p[i] = tf32r(p[i] * inv);

    int zend = min(T, ((t >> 7) + 1) << 7);
    for (int i = n + tid; i < zend; i += 256) p[i] = 0.f;
}

// ---------------------------------------------------------------------------
extern "C" void kernel_launch(void* const* d_in, const int* in_sizes, int n_in,
                              void* d_out, int out_size)
{
    const float* x  = (const float*)d_in[0];   // [B,T,C]
    const float* Wk = (const float*)d_in[1];   // [H,C]
    const float* Wq = (const float*)d_in[2];   // [H,C]
    const float* Wv = (const float*)d_in[3];   // [H,C]
    float* out = (float*)d_out;                // [B,T,H]

    float* q;  cudaGetSymbolAddress((void**)&q,  g_q);
    float* k;  cudaGetSymbolAddress((void**)&k,  g_k);
    float* vt; cudaGetSymbolAddress((void**)&vt, g_v);
    float* s;  cudaGetSymbolAddress((void**)&s,  g_s);
    float* xr; cudaGetSymbolAddress((void**)&xr, g_xr);
    float* wr; cudaGetSymbolAddress((void**)&wr, g_wr);

    const int M = BB * TT;                 // 8192
    const int HC = HH * CC;                // 2M
    const float scale = rsqrtf((float)HH);

    // 0) pre-round operands to tf32 (RNA: unbiased)
    int nx = BB * TT * CC;
    round_pass<<<(nx / 4 + 255) / 256, 256>>>(x, xr, nx);
    round_pass<<<(HC / 4 + 255) / 256, 256>>>(Wk, wr,          HC);
    round_pass<<<(HC / 4 + 255) / 256, 256>>>(Wq, wr + HC,     HC);
    round_pass<<<(HC / 4 + 255) / 256, 256>>>(Wv, wr + 2 * HC, HC);

    // 1) Q,K projections: [M,C] x [H,C]^T -> [M,H]  (outputs tf32-rounded)
    dim3 gp(HH / BN, M / BM, 1);
    mma_nt<<<gp, 256>>>(xr, wr + HC, q, M, HH, CC, 1.f, 0, 0, 1, 0, 0, 0);
    mma_nt<<<gp, 256>>>(xr, wr,      k, M, HH, CC, 1.f, 0, 0, 1, 0, 0, 0);

    // 1b) Vt = Wv * x_b^T -> [H,T] per batch (transposed V, coalesced)
    dim3 gv(TT / BN, HH / BM, BB);
    mma_nt<<<gv, 256>>>(wr + 2 * HC, xr, vt, HH, TT, CC, 1.f, 0, 0, 1,
                        0, (long long)TT * CC, (long long)HH * TT);

    // 2) S_b = scale * Q_b K_b^T  (causal tile skip)
    dim3 gs(TT / BN, TT / BM, BB);
    mma_nt<<<gs, 256>>>(q, k, s, TT, TT, HH, scale, 1, 0, 0,
                        (long long)TT * HH, (long long)TT * HH,
                        (long long)TT * TT);

    // 3) softmax (rounds P) + zero diag-block tail
    softmax_causal<<<BB * TT, 256>>>(s, TT);

    // 4) O_b = P_b Vt_b^T  (k-limit per block row)
    dim3 go(HH / BN, TT / BM, BB);
    mma_nt<<<go, 256>>>(s, vt, out, TT, HH, TT, 1.f, 0, 1, 0,
                        (long long)TT * TT, (long long)HH * TT,
                        (long long)TT * HH);
}

// round 14
// speedup vs baseline: 4.5883x; 1.3822x over previous
#include <cuda_runtime.h>
#include <cstdint>
#include <math.h>

#define BB 4
#define TT 2048
#define CC 1024
#define HH 2048

// ---- scratch (device globals; allocation-free rule) -----------------------
__device__ float g_q[(size_t)BB * TT * HH];
__device__ float g_k[(size_t)BB * TT * HH];
__device__ float g_v[(size_t)BB * TT * HH];      // V TRANSPOSED: [B][H][T]
__device__ float g_s[(size_t)BB * TT * TT];
__device__ float g_xr[(size_t)BB * TT * CC];     // tf32-rounded x
__device__ float g_wr[(size_t)3 * HH * CC];      // tf32-rounded Wk|Wq|Wv

// ---- helpers --------------------------------------------------------------
__device__ __forceinline__ uint32_t smem_u32(const void* p) {
    uint32_t a;
    asm("{ .reg .u64 t; cvta.to.shared.u64 t, %1; cvt.u32.u64 %0, t; }"
        : "=r"(a) : "l"(p));
    return a;
}
__device__ __forceinline__ float tf32r(float v) {
    uint32_t u;
    asm("cvt.rna.tf32.f32 %0, %1;" : "=r"(u) : "f"(v));
    return __uint_as_float(u);
}

#define CP16(dst, src) \
    asm volatile("cp.async.cg.shared.global [%0], [%1], 16;" \
                 :: "r"(dst), "l"(src))
#define CP_COMMIT() asm volatile("cp.async.commit_group;" ::: "memory")
#define CP_WAIT1()  asm volatile("cp.async.wait_group 1;" ::: "memory")
#define CP_WAIT0()  asm volatile("cp.async.wait_group 0;" ::: "memory")

#define LDSM4(r0, r1, r2, r3, a) \
    asm volatile("ldmatrix.sync.aligned.m8n8.x4.shared.b16 {%0,%1,%2,%3}, [%4];" \
                 : "=r"(r0), "=r"(r1), "=r"(r2), "=r"(r3) : "r"(a))

#define MMA8(d, a, b0, b1) \
    asm volatile("mma.sync.aligned.m16n8k8.row.col.f32.tf32.tf32.f32 " \
        "{%0,%1,%2,%3}, {%4,%5,%6,%7}, {%8,%9}, {%0,%1,%2,%3};" \
        : "+f"((d)[0]), "+f"((d)[1]), "+f"((d)[2]), "+f"((d)[3]) \
        : "r"((a)[0]), "r"((a)[1]), "r"((a)[2]), "r"((a)[3]), \
          "r"(b0), "r"(b1))

// ---- GEMM config ----------------------------------------------------------
#define BM 128
#define BN 128
#define BK 32
#define PADK 36                         // floats per smem row (144B; 9x16B units)
#define TBUF (BM * PADK)                // floats per buffer (4608)
#define TBUF_B (TBUF * 4)               // 18432 bytes
#define SMEM_BYTES (4 * TBUF_B)         // A[2] + B[2] = 73728

// ---------------------------------------------------------------------------
// C[M,N] = scale * A[M,K] * B[N,K]^T  (row-major, K contiguous)
// tf32 mma.sync m16n8k8, 128x128x32 tiles, 8 warps (2x4), warp tile 64x32,
// cp.async double buffer, all-x4 ldmatrix.
// causal: skip tiles bx > by.  klimit: K bounded at (by+1)*BM.
// round_out: RNA-round outputs to tf32 (tensors feeding another MMA).
// ---------------------------------------------------------------------------
__global__ __launch_bounds__(256, 2)
void mma_nt(const float* __restrict__ A, const float* __restrict__ B,
            float* __restrict__ C, int M, int N, int K, float scale,
            int causal, int klimit, int round_out,
            long long sA, long long sB, long long sC)
{
    int bx = blockIdx.x, by = blockIdx.y, bz = blockIdx.z;
    if (causal && bx > by) return;
    A += (long long)bz * sA;
    B += (long long)bz * sB;
    C += (long long)bz * sC;

    extern __shared__ float dsm[];
    float* As = dsm;                    // [2][TBUF]
    float* Bs = dsm + 2 * TBUF;         // [2][TBUF]

    int tid = threadIdx.x;
    int lane = tid & 31, wid = tid >> 5;
    int warp_m = wid >> 2;              // 0..1 -> 64-row half
    int warp_n = wid & 3;               // 0..3 -> 32-col quarter

    const float* Ab = A + (size_t)(by * BM) * K;
    const float* Bb = B + (size_t)(bx * BN) * K;

    int kend = klimit ? min(K, (by + 1) * BM) : K;
    int nt = kend / BK;

    uint32_t as0 = smem_u32(As);
    uint32_t bs0 = smem_u32(Bs);

    // cp.async: per matrix 128 rows x 8 chunks(16B); 256 thr x 4 chunks.
    int crow = tid >> 3;                // 0..31 (+32*i)
    int ccol = (tid & 7) * 4;           // float offset in row
    uint32_t dA = as0 + (uint32_t)(crow * PADK + ccol) * 4;
    uint32_t dB = bs0 + (uint32_t)(crow * PADK + ccol) * 4;
    const float* sAp = Ab + (size_t)crow * K + ccol;
    const float* sBp = Bb + (size_t)crow * K + ccol;
    const uint32_t rstep = 32 * PADK * 4;   // 32 rows in smem bytes

    // ldmatrix bases
    uint32_t aAddr = as0 + (uint32_t)(((warp_m * 64 + (lane & 15)) * PADK
                                       + (lane >> 4) * 4) * 4);
    uint32_t bAddr = bs0 + (uint32_t)(((warp_n * 32 + (lane & 7)
                                        + ((lane >> 4) & 1) * 8) * PADK
                                       + ((lane >> 3) & 1) * 4) * 4);

    float acc[4][4][4];
#pragma unroll
    for (int i = 0; i < 4; i++)
#pragma unroll
        for (int j = 0; j < 4; j++)
#pragma unroll
            for (int r = 0; r < 4; r++) acc[i][j][r] = 0.f;

    // preload tile 0
#pragma unroll
    for (int i = 0; i < 4; i++) {
        CP16(dA + i * rstep, sAp + (size_t)(i * 32) * K);
        CP16(dB + i * rstep, sBp + (size_t)(i * 32) * K);
    }
    CP_COMMIT();

    for (int t = 0; t < nt; t++) {
        uint32_t boff = (uint32_t)(t & 1) * TBUF_B;
        if (t + 1 < nt) {
            uint32_t nboff = (uint32_t)((t + 1) & 1) * TBUF_B;
            size_t ko = (size_t)(t + 1) * BK;
#pragma unroll
            for (int i = 0; i < 4; i++) {
                CP16(dA + nboff + i * rstep, sAp + (size_t)(i * 32) * K + ko);
                CP16(dB + nboff + i * rstep, sBp + (size_t)(i * 32) * K + ko);
            }
            CP_COMMIT();
            CP_WAIT1();
        } else {
            CP_WAIT0();
        }
        __syncthreads();

#pragma unroll
        for (int ks = 0; ks < 4; ks++) {
            uint32_t a[4][4], b[2][4];
#pragma unroll
            for (int mi = 0; mi < 4; mi++)
                LDSM4(a[mi][0], a[mi][1], a[mi][2], a[mi][3],
                      aAddr + boff + (uint32_t)(mi * 16 * PADK * 4 + ks * 32));
#pragma unroll
            for (int g = 0; g < 2; g++)
                LDSM4(b[g][0], b[g][1], b[g][2], b[g][3],
                      bAddr + boff + (uint32_t)(g * 16 * PADK * 4 + ks * 32));
#pragma unroll
            for (int mi = 0; mi < 4; mi++)
#pragma unroll
                for (int g = 0; g < 2; g++) {
                    MMA8(acc[mi][2 * g],     a[mi], b[g][0], b[g][1]);
                    MMA8(acc[mi][2 * g + 1], a[mi], b[g][2], b[g][3]);
                }
        }
        __syncthreads();
    }

    // epilogue
#pragma unroll
    for (int mi = 0; mi < 4; mi++) {
#pragma unroll
        for (int ni = 0; ni < 4; ni++) {
            int r0 = by * BM + warp_m * 64 + mi * 16 + (lane >> 2);
            int c  = bx * BN + warp_n * 32 + ni * 8 + 2 * (lane & 3);
            float2 v0, v1;
            v0.x = acc[mi][ni][0] * scale; v0.y = acc[mi][ni][1] * scale;
            v1.x = acc[mi][ni][2] * scale; v1.y = acc[mi][ni][3] * scale;
            if (round_out) {
                v0.x = tf32r(v0.x); v0.y = tf32r(v0.y);
                v1.x = tf32r(v1.x); v1.y = tf32r(v1.y);
            }
            *(float2*)(C + (size_t)r0 * N + c)       = v0;
            *(float2*)(C + (size_t)(r0 + 8) * N + c) = v1;
        }
    }
}

// ---- tf32 pre-rounding pass ----------------------------------------------
__global__ __launch_bounds__(256)
void round_pass(const float* __restrict__ in, float* __restrict__ out, int n)
{
    int i = (blockIdx.x * 256 + threadIdx.x) * 4;
    if (i < n) {
        float4 v = *(const float4*)(in + i);
        v.x = tf32r(v.x); v.y = tf32r(v.y); v.z = tf32r(v.z); v.w = tf32r(v.w);
        *(float4*)(out + i) = v;
    }
}

// ---- causal softmax (in-place, float4), rounds P to tf32, zero diag tail --
__device__ __forceinline__ float warp_max(float v) {
#pragma unroll
    for (int o = 16; o; o >>= 1) v = fmaxf(v, __shfl_xor_sync(0xffffffffu, v, o));
    return v;
}
__device__ __forceinline__ float warp_sum(float v) {
#pragma unroll
    for (int o = 16; o; o >>= 1) v += __shfl_xor_sync(0xffffffffu, v, o);
    return v;
}

__global__ __launch_bounds__(256)
void softmax_causal(float* __restrict__ S, int T)
{
    int row = blockIdx.x;
    int b = row / T;
    int t = row - b * T;
    float* p = S + (long long)b * T * T + (long long)t * T;
    float4* p4 = (float4*)p;
    int n = t + 1;
    int n4 = n >> 2;

    int tid = threadIdx.x;
    int lane = tid & 31, wid = tid >> 5;
    __shared__ float red[8];

    float m = -INFINITY;
    for (int i = tid; i < n4; i += 256) {
        float4 v = p4[i];
        m = fmaxf(m, fmaxf(fmaxf(v.x, v.y), fmaxf(v.z, v.w)));
    }
    for (int i = n4 * 4 + tid; i < n; i += 256) m = fmaxf(m, p[i]);
    m = warp_max(m);
    if (lane == 0) red[wid] = m;
    __syncthreads();
    if (wid == 0) {
        float x = (lane < 8) ? red[lane] : -INFINITY;
        x = warp_max(x);
        if (lane == 0) red[0] = x;
    }
    __syncthreads();
    m = red[0];
    __syncthreads();

    float s = 0.f;
    for (int i = tid; i < n4; i += 256) {
        float4 v = p4[i];
        v.x = __expf(v.x - m); v.y = __expf(v.y - m);
        v.z = __expf(v.z - m); v.w = __expf(v.w - m);
        s += v.x + v.y + v.z + v.w;
        p4[i] = v;
    }
    for (int i = n4 * 4 + tid; i < n; i += 256) {
        float e = __expf(p[i] - m);
        p[i] = e;
        s += e;
    }
    s = warp_sum(s);
    if (lane == 0) red[wid] = s;
    __syncthreads();
    if (wid == 0) {
        float x = (lane < 8) ? red[lane] : 0.f;
        x = warp_sum(x);
        if (lane == 0) red[0] = x;
    }
    __syncthreads();
    float inv = 1.f / red[0];

    for (int i = tid; i < n4; i += 256) {
        float4 v = p4[i];
        v.x = tf32r(v.x * inv); v.y = tf32r(v.y * inv);
        v.z = tf32r(v.z * inv); v.w = tf32r(v.w * inv);
        p4[i] = v;
    }
    for (int i = n4 * 4 + tid; i < n; i += 256) p[i] = tf32r(p[i] * inv);

    int zend = min(T, ((t >> 7) + 1) << 7);
    for (int i = n + tid; i < zend; i += 256) p[i] = 0.f;
}

// ---------------------------------------------------------------------------
extern "C" void kernel_launch(void* const* d_in, const int* in_sizes, int n_in,
                              void* d_out, int out_size)
{
    const float* x  = (const float*)d_in[0];   // [B,T,C]
    const float* Wk = (const float*)d_in[1];   // [H,C]
    const float* Wq = (const float*)d_in[2];   // [H,C]
    const float* Wv = (const float*)d_in[3];   // [H,C]
    float* out = (float*)d_out;                // [B,T,H]

    float* q;  cudaGetSymbolAddress((void**)&q,  g_q);
    float* k;  cudaGetSymbolAddress((void**)&k,  g_k);
    float* vt; cudaGetSymbolAddress((void**)&vt, g_v);
    float* s;  cudaGetSymbolAddress((void**)&s,  g_s);
    float* xr; cudaGetSymbolAddress((void**)&xr, g_xr);
    float* wr; cudaGetSymbolAddress((void**)&wr, g_wr);

    cudaFuncSetAttribute(mma_nt, cudaFuncAttributeMaxDynamicSharedMemorySize,
                         SMEM_BYTES);

    const int M = BB * TT;                 // 8192
    const int HC = HH * CC;                // 2M
    const float scale = rsqrtf((float)HH);

    // 0) pre-round operands to tf32 (RNA: unbiased)
    int nx = BB * TT * CC;
    round_pass<<<(nx / 4 + 255) / 256, 256>>>(x, xr, nx);
    round_pass<<<(HC / 4 + 255) / 256, 256>>>(Wk, wr,          HC);
    round_pass<<<(HC / 4 + 255) / 256, 256>>>(Wq, wr + HC,     HC);
    round_pass<<<(HC / 4 + 255) / 256, 256>>>(Wv, wr + 2 * HC, HC);

    // 1) Q,K projections: [M,C] x [H,C]^T -> [M,H]  (outputs tf32-rounded)
    dim3 gp(HH / BN, M / BM, 1);
    mma_nt<<<gp, 256, SMEM_BYTES>>>(xr, wr + HC, q, M, HH, CC, 1.f,
                                    0, 0, 1, 0, 0, 0);
    mma_nt<<<gp, 256, SMEM_BYTES>>>(xr, wr,      k, M, HH, CC, 1.f,
                                    0, 0, 1, 0, 0, 0);

    // 1b) Vt = Wv * x_b^T -> [H,T] per batch (transposed V, coalesced)
    dim3 gv(TT / BN, HH / BM, BB);
    mma_nt<<<gv, 256, SMEM_BYTES>>>(wr + 2 * HC, xr, vt, HH, TT, CC, 1.f,
                                    0, 0, 1,
                                    0, (long long)TT * CC, (long long)HH * TT);

    // 2) S_b = scale * Q_b K_b^T  (causal tile skip)
    dim3 gs(TT / BN, TT / BM, BB);
    mma_nt<<<gs, 256, SMEM_BYTES>>>(q, k, s, TT, TT, HH, scale, 1, 0, 0,
                                    (long long)TT * HH, (long long)TT * HH,
                                    (long long)TT * TT);

    // 3) softmax (rounds P) + zero diag-block tail
    softmax_causal<<<BB * TT, 256>>>(s, TT);

    // 4) O_b = P_b Vt_b^T  (k-limit per block row)
    dim3 go(HH / BN, TT / BM, BB);
    mma_nt<<<go, 256, SMEM_BYTES>>>(s, vt, out, TT, HH, TT, 1.f, 0, 1, 0,
                                    (long long)TT * TT, (long long)HH * TT,
                                    (long long)TT * HH);
}